// round 9
// baseline (speedup 1.0000x reference)
#include <cuda_runtime.h>
#include <cuda_bf16.h>
#include <math.h>

// Spherical harmonics Re(Y_l^m), l=0..3, scipy sph_harm convention.
// Output layout: [Y0 (N*1) | Y1 (N*3) | Y2 (N*5) | Y3 (N*7)].
//
// Round-8 recipe with doubled slab (1024 points/block) for longer per-region
// write bursts: 256 threads x 4 points, s_in/l1 union, 60 KB dynamic smem,
// coalesced float4 I/O, streaming-hint stores.

#define C_Y00   0.28209479177387814f
#define C_Y10   0.48860251190291992f
#define C_Y11   0.34549414947133547f
#define C_Y20   0.31539156525252005f
#define C_Y21   0.77254840404659256f
#define C_Y22   0.38627420202329628f
#define C_Y30   0.37317633259011540f
#define C_Y31   0.32318018411415066f
#define C_Y32   1.02198547643328236f
#define C_Y33   0.41722382363278409f

#define THREADS 256
#define PPT     4
#define PPB     (THREADS * PPT)     // 1024
#define IN_F4   ((PPB * 3) / 4)     // 768
#define SMEM_BYTES (PPB * 15 * 4)   // 61440

__global__ __launch_bounds__(THREADS)
void sh_l3_staged_kernel(const float* __restrict__ dirs,
                         float* __restrict__ out, int n) {
    extern __shared__ float smem[];
    float* s1buf = smem;              // PPB*3: input slab, then l=1 staging
    float* s2    = smem + PPB * 3;    // PPB*5
    float* s3    = smem + PPB * 8;    // PPB*7

    const int tid = threadIdx.x;
    const long long base_pt = (long long)blockIdx.x * PPB;
    const long long nll = n;

    // ---- Phase 0: coalesced float4 load of input slab ----
    {
        const float4* in4 = (const float4*)dirs;
        const long long total4 = (nll * 3) >> 2;
        const long long base4 = base_pt * 3 / 4;    // PPB*3 divisible by 4
        #pragma unroll
        for (int k = 0; k < 3; k++) {
            int j = tid + k * THREADS;               // 768 = 3*256 exactly
            long long g4 = base4 + j;
            if (g4 < total4) ((float4*)s1buf)[j] = __ldg(&in4[g4]);
        }
    }
    __syncthreads();

    // ---- Phase 1a: pull all points' xyz into registers ----
    float xr[PPT], yr[PPT], zr[PPT];
    #pragma unroll
    for (int p = 0; p < PPT; p++) {
        const int lp = tid + p * THREADS;
        xr[p] = s1buf[lp * 3 + 0];
        yr[p] = s1buf[lp * 3 + 1];
        zr[p] = s1buf[lp * 3 + 2];
    }
    __syncthreads();   // reads done before the l=1 scatter overwrites s1buf

    // ---- Phase 1b: compute + scatter (odd strides: bank-conflict-free) ----
    #pragma unroll
    for (int p = 0; p < PPT; p++) {
        const int lp = tid + p * THREADS;
        const long long gp = base_pt + lp;
        if (gp >= nll) break;

        float x = xr[p], y = yr[p], z = zr[p];

        float r   = sqrtf(x * x + y * y + z * z);
        float ct  = z / (r + 1e-8f);
        float ct2 = ct * ct;
        float st  = sqrtf(fmaxf(1.0f - ct2, 0.0f));
        float st2 = st * st;

        float rho2 = x * x + y * y;
        float c1, c2, c3;
        if (rho2 > 0.0f) {
            float inv_rho = rsqrtf(rho2);
            c1 = x * inv_rho;
            c2 = 2.0f * c1 * c1 - 1.0f;
            c3 = c1 * (2.0f * c2 - 1.0f);
        } else {
            c1 = 1.0f; c2 = 1.0f; c3 = 1.0f;
        }

        float y10 = C_Y10 * ct;
        float y11 = -C_Y11 * st * c1;
        s1buf[lp * 3 + 0] = -y11;
        s1buf[lp * 3 + 1] =  y10;
        s1buf[lp * 3 + 2] =  y11;

        float y20 = C_Y20 * (3.0f * ct2 - 1.0f);
        float y21 = -C_Y21 * ct * st * c1;
        float y22 =  C_Y22 * st2 * c2;
        s2[lp * 5 + 0] =  y22;
        s2[lp * 5 + 1] = -y21;
        s2[lp * 5 + 2] =  y20;
        s2[lp * 5 + 3] =  y21;
        s2[lp * 5 + 4] =  y22;

        float y30 =  C_Y30 * ct * (5.0f * ct2 - 3.0f);
        float y31 = -C_Y31 * (5.0f * ct2 - 1.0f) * st * c1;
        float y32 =  C_Y32 * ct * st2 * c2;
        float y33 = -C_Y33 * st * st2 * c3;
        s3[lp * 7 + 0] = -y33;
        s3[lp * 7 + 1] =  y32;
        s3[lp * 7 + 2] = -y31;
        s3[lp * 7 + 3] =  y30;
        s3[lp * 7 + 4] =  y31;
        s3[lp * 7 + 5] =  y32;
        s3[lp * 7 + 6] =  y33;
    }
    __syncthreads();

    // ---- Phase 2: coalesced float4 streaming flush ----
    // l = 0: pure constant region, 256 float4 per block (1 per thread).
    {
        long long fbase = base_pt;
        long long rem = nll - fbase;
        long long idx = (long long)tid * 4;
        float4 v = make_float4(C_Y00, C_Y00, C_Y00, C_Y00);
        if (idx + 4 <= rem) {
            __stcs((float4*)(out + fbase + idx), v);
        } else {
            for (int e = 0; e < 4; e++)
                if (idx + e < rem) out[fbase + idx + e] = C_Y00;
        }
    }

    // l = 1: 768 float4
    {
        float* gbase = out + nll;
        long long fbase = base_pt * 3;
        long long rem = nll * 3 - fbase;
        #pragma unroll
        for (int k = 0; k < 3; k++) {
            int j = tid + k * THREADS;
            long long idx = (long long)j * 4;
            if (idx + 4 <= rem) {
                __stcs((float4*)(gbase + fbase + idx), ((const float4*)s1buf)[j]);
            } else {
                for (int e = 0; e < 4; e++)
                    if (idx + e < rem) gbase[fbase + idx + e] = s1buf[idx + e];
            }
        }
    }

    // l = 2: 1280 float4
    {
        float* gbase = out + 4 * nll;
        long long fbase = base_pt * 5;
        long long rem = nll * 5 - fbase;
        #pragma unroll
        for (int k = 0; k < 5; k++) {
            int j = tid + k * THREADS;
            long long idx = (long long)j * 4;
            if (idx + 4 <= rem) {
                __stcs((float4*)(gbase + fbase + idx), ((const float4*)s2)[j]);
            } else {
                for (int e = 0; e < 4; e++)
                    if (idx + e < rem) gbase[fbase + idx + e] = s2[idx + e];
            }
        }
    }

    // l = 3: 1792 float4
    {
        float* gbase = out + 9 * nll;
        long long fbase = base_pt * 7;
        long long rem = nll * 7 - fbase;
        #pragma unroll
        for (int k = 0; k < 7; k++) {
            int j = tid + k * THREADS;
            long long idx = (long long)j * 4;
            if (idx + 4 <= rem) {
                __stcs((float4*)(gbase + fbase + idx), ((const float4*)s3)[j]);
            } else {
                for (int e = 0; e < 4; e++)
                    if (idx + e < rem) gbase[fbase + idx + e] = s3[idx + e];
            }
        }
    }
}

extern "C" void kernel_launch(void* const* d_in, const int* in_sizes, int n_in,
                              void* d_out, int out_size) {
    const float* dirs = (const float*)d_in[0];
    float* out = (float*)d_out;
    int n = in_sizes[0] / 3;

    static int smem_set = 0;
    if (!smem_set) {
        cudaFuncSetAttribute(sh_l3_staged_kernel,
                             cudaFuncAttributeMaxDynamicSharedMemorySize, SMEM_BYTES);
        smem_set = 1;
    }

    int blocks = (n + PPB - 1) / PPB;
    sh_l3_staged_kernel<<<blocks, THREADS, SMEM_BYTES>>>(dirs, out, n);
}

// round 10
// speedup vs baseline: 1.0079x; 1.0079x over previous
#include <cuda_runtime.h>
#include <cuda_bf16.h>
#include <math.h>

// Spherical harmonics Re(Y_l^m), l=0..3, scipy sph_harm convention.
// Output layout: [Y0 (N*1) | Y1 (N*3) | Y2 (N*5) | Y3 (N*7)].
//
// Converged configuration (round-8 best, 48.2us profiled ~= 82% effective HBM):
//   256 threads x 2 points = 512-point slab per block,
//   s_in unioned with l=1 staging -> 30 KB smem,
//   all global I/O contiguous float4,
//   __ldcs streaming reads + __stcs streaming stores (minimal L2 contention).

#define C_Y00   0.28209479177387814f
#define C_Y10   0.48860251190291992f
#define C_Y11   0.34549414947133547f
#define C_Y20   0.31539156525252005f
#define C_Y21   0.77254840404659256f
#define C_Y22   0.38627420202329628f
#define C_Y30   0.37317633259011540f
#define C_Y31   0.32318018411415066f
#define C_Y32   1.02198547643328236f
#define C_Y33   0.41722382363278409f

#define THREADS 256
#define PPT     2
#define PPB     (THREADS * PPT)     // 512
#define IN_F4   ((PPB * 3) / 4)     // 384

__global__ __launch_bounds__(THREADS)
void sh_l3_staged_kernel(const float* __restrict__ dirs,
                         float* __restrict__ out, int n) {
    __shared__ float s1buf[PPB * 3];  // 6 KB: input slab, then l=1 staging
    __shared__ float s2[PPB * 5];     // 10 KB
    __shared__ float s3[PPB * 7];     // 14 KB  -> 30 KB total

    const int tid = threadIdx.x;
    const long long base_pt = (long long)blockIdx.x * PPB;
    const long long nll = n;

    // ---- Phase 0: coalesced float4 streaming load of input slab ----
    {
        const float4* in4 = (const float4*)dirs;
        const long long total4 = (nll * 3) >> 2;
        const long long base4 = base_pt * 3 / 4;    // PPB*3 divisible by 4
        #pragma unroll
        for (int k = 0; k < 2; k++) {
            int j = tid + k * THREADS;
            if (j < IN_F4) {
                long long g4 = base4 + j;
                if (g4 < total4) ((float4*)s1buf)[j] = __ldcs(&in4[g4]);
            }
        }
    }
    __syncthreads();

    // ---- Phase 1a: pull both points' xyz into registers ----
    float xr[PPT], yr[PPT], zr[PPT];
    #pragma unroll
    for (int p = 0; p < PPT; p++) {
        const int lp = tid + p * THREADS;
        xr[p] = s1buf[lp * 3 + 0];
        yr[p] = s1buf[lp * 3 + 1];
        zr[p] = s1buf[lp * 3 + 2];
    }
    __syncthreads();   // all reads of s1buf done before the l=1 scatter reuses it

    // ---- Phase 1b: compute + scatter (odd strides: bank-conflict-free) ----
    #pragma unroll
    for (int p = 0; p < PPT; p++) {
        const int lp = tid + p * THREADS;
        const long long gp = base_pt + lp;
        if (gp >= nll) break;

        float x = xr[p], y = yr[p], z = zr[p];

        float r   = sqrtf(x * x + y * y + z * z);
        float ct  = z / (r + 1e-8f);
        float ct2 = ct * ct;
        float st  = sqrtf(fmaxf(1.0f - ct2, 0.0f));
        float st2 = st * st;

        float rho2 = x * x + y * y;
        float c1, c2, c3;
        if (rho2 > 0.0f) {
            float inv_rho = rsqrtf(rho2);
            c1 = x * inv_rho;
            c2 = 2.0f * c1 * c1 - 1.0f;
            c3 = c1 * (2.0f * c2 - 1.0f);
        } else {
            c1 = 1.0f; c2 = 1.0f; c3 = 1.0f;
        }

        float y10 = C_Y10 * ct;
        float y11 = -C_Y11 * st * c1;
        s1buf[lp * 3 + 0] = -y11;
        s1buf[lp * 3 + 1] =  y10;
        s1buf[lp * 3 + 2] =  y11;

        float y20 = C_Y20 * (3.0f * ct2 - 1.0f);
        float y21 = -C_Y21 * ct * st * c1;
        float y22 =  C_Y22 * st2 * c2;
        s2[lp * 5 + 0] =  y22;
        s2[lp * 5 + 1] = -y21;
        s2[lp * 5 + 2] =  y20;
        s2[lp * 5 + 3] =  y21;
        s2[lp * 5 + 4] =  y22;

        float y30 =  C_Y30 * ct * (5.0f * ct2 - 3.0f);
        float y31 = -C_Y31 * (5.0f * ct2 - 1.0f) * st * c1;
        float y32 =  C_Y32 * ct * st2 * c2;
        float y33 = -C_Y33 * st * st2 * c3;
        s3[lp * 7 + 0] = -y33;
        s3[lp * 7 + 1] =  y32;
        s3[lp * 7 + 2] = -y31;
        s3[lp * 7 + 3] =  y30;
        s3[lp * 7 + 4] =  y31;
        s3[lp * 7 + 5] =  y32;
        s3[lp * 7 + 6] =  y33;
    }
    __syncthreads();

    // ---- Phase 2: coalesced float4 streaming flush ----
    // l = 0: pure constant region, 128 float4 per block.
    if (tid < PPB / 4) {
        long long fbase = base_pt;
        long long rem = nll - fbase;
        long long idx = (long long)tid * 4;
        float4 v = make_float4(C_Y00, C_Y00, C_Y00, C_Y00);
        if (idx + 4 <= rem) {
            __stcs((float4*)(out + fbase + idx), v);
        } else {
            for (int e = 0; e < 4; e++)
                if (idx + e < rem) out[fbase + idx + e] = C_Y00;
        }
    }

    // l = 1: 384 float4
    {
        float* gbase = out + nll;
        long long fbase = base_pt * 3;
        long long rem = nll * 3 - fbase;
        #pragma unroll
        for (int k = 0; k < 2; k++) {
            int j = tid + k * THREADS;
            if (j < IN_F4) {
                long long idx = (long long)j * 4;
                if (idx + 4 <= rem) {
                    __stcs((float4*)(gbase + fbase + idx), ((const float4*)s1buf)[j]);
                } else {
                    for (int e = 0; e < 4; e++)
                        if (idx + e < rem) gbase[fbase + idx + e] = s1buf[idx + e];
                }
            }
        }
    }

    // l = 2: 640 float4
    {
        float* gbase = out + 4 * nll;
        long long fbase = base_pt * 5;
        long long rem = nll * 5 - fbase;
        #pragma unroll
        for (int k = 0; k < 3; k++) {
            int j = tid + k * THREADS;
            if (j < (PPB * 5) / 4) {
                long long idx = (long long)j * 4;
                if (idx + 4 <= rem) {
                    __stcs((float4*)(gbase + fbase + idx), ((const float4*)s2)[j]);
                } else {
                    for (int e = 0; e < 4; e++)
                        if (idx + e < rem) gbase[fbase + idx + e] = s2[idx + e];
                }
            }
        }
    }

    // l = 3: 896 float4
    {
        float* gbase = out + 9 * nll;
        long long fbase = base_pt * 7;
        long long rem = nll * 7 - fbase;
        #pragma unroll
        for (int k = 0; k < 4; k++) {
            int j = tid + k * THREADS;
            if (j < (PPB * 7) / 4) {
                long long idx = (long long)j * 4;
                if (idx + 4 <= rem) {
                    __stcs((float4*)(gbase + fbase + idx), ((const float4*)s3)[j]);
                } else {
                    for (int e = 0; e < 4; e++)
                        if (idx + e < rem) gbase[fbase + idx + e] = s3[idx + e];
                }
            }
        }
    }
}

extern "C" void kernel_launch(void* const* d_in, const int* in_sizes, int n_in,
                              void* d_out, int out_size) {
    const float* dirs = (const float*)d_in[0];
    float* out = (float*)d_out;
    int n = in_sizes[0] / 3;

    int blocks = (n + PPB - 1) / PPB;
    sh_l3_staged_kernel<<<blocks, THREADS>>>(dirs, out, n);
}

// round 11
// speedup vs baseline: 1.0316x; 1.0235x over previous
#include <cuda_runtime.h>
#include <cuda_bf16.h>
#include <math.h>

// Spherical harmonics Re(Y_l^m), l=0..3, scipy sph_harm convention.
// Output layout: [Y0 (N*1) | Y1 (N*3) | Y2 (N*5) | Y3 (N*7)].
//
// Converged config: 256 threads x 2 points = 512-point slab, s_in/l1 smem
// union (30 KB), coalesced float4 I/O, __stcs streaming stores.
// Full-slab kernel is guard-free with 32-bit indexing; a scalar tail kernel
// covers n % 512 remainder points (n = 4.19M -> no tail in practice).

#define C_Y00   0.28209479177387814f
#define C_Y10   0.48860251190291992f
#define C_Y11   0.34549414947133547f
#define C_Y20   0.31539156525252005f
#define C_Y21   0.77254840404659256f
#define C_Y22   0.38627420202329628f
#define C_Y30   0.37317633259011540f
#define C_Y31   0.32318018411415066f
#define C_Y32   1.02198547643328236f
#define C_Y33   0.41722382363278409f

#define THREADS 256
#define PPT     2
#define PPB     (THREADS * PPT)     // 512
#define IN_F4   ((PPB * 3) / 4)     // 384

__global__ __launch_bounds__(THREADS)
void sh_l3_full_kernel(const float* __restrict__ dirs,
                       float* __restrict__ out, int n) {
    __shared__ float s1buf[PPB * 3];  // 6 KB: input slab, then l=1 staging
    __shared__ float s2[PPB * 5];     // 10 KB
    __shared__ float s3[PPB * 7];     // 14 KB  -> 30 KB

    const int tid = threadIdx.x;
    const int base_pt = blockIdx.x * PPB;

    // ---- Phase 0: coalesced float4 load, 384 float4 = 256 + 128 ----
    {
        const float4* in4 = (const float4*)dirs + (base_pt / 4) * 3;
        ((float4*)s1buf)[tid] = __ldg(&in4[tid]);
        if (tid < IN_F4 - THREADS)                       // 128 lanes
            ((float4*)s1buf)[tid + THREADS] = __ldg(&in4[tid + THREADS]);
    }
    __syncthreads();

    // ---- Phase 1a: pull both points' xyz into registers ----
    float xr[PPT], yr[PPT], zr[PPT];
    #pragma unroll
    for (int p = 0; p < PPT; p++) {
        const int lp = tid + p * THREADS;
        xr[p] = s1buf[lp * 3 + 0];
        yr[p] = s1buf[lp * 3 + 1];
        zr[p] = s1buf[lp * 3 + 2];
    }
    __syncthreads();   // reads complete before l=1 scatter reuses s1buf

    // ---- Phase 1b: compute + scatter (odd strides: conflict-free) ----
    #pragma unroll
    for (int p = 0; p < PPT; p++) {
        const int lp = tid + p * THREADS;

        float x = xr[p], y = yr[p], z = zr[p];

        float r   = sqrtf(x * x + y * y + z * z);
        float ct  = z / (r + 1e-8f);
        float ct2 = ct * ct;
        float st  = sqrtf(fmaxf(1.0f - ct2, 0.0f));
        float st2 = st * st;

        float rho2 = x * x + y * y;
        float c1, c2, c3;
        if (rho2 > 0.0f) {
            float inv_rho = rsqrtf(rho2);
            c1 = x * inv_rho;
            c2 = 2.0f * c1 * c1 - 1.0f;
            c3 = c1 * (2.0f * c2 - 1.0f);
        } else {
            c1 = 1.0f; c2 = 1.0f; c3 = 1.0f;
        }

        float y10 = C_Y10 * ct;
        float y11 = -C_Y11 * st * c1;
        s1buf[lp * 3 + 0] = -y11;
        s1buf[lp * 3 + 1] =  y10;
        s1buf[lp * 3 + 2] =  y11;

        float y20 = C_Y20 * (3.0f * ct2 - 1.0f);
        float y21 = -C_Y21 * ct * st * c1;
        float y22 =  C_Y22 * st2 * c2;
        s2[lp * 5 + 0] =  y22;
        s2[lp * 5 + 1] = -y21;
        s2[lp * 5 + 2] =  y20;
        s2[lp * 5 + 3] =  y21;
        s2[lp * 5 + 4] =  y22;

        float y30 =  C_Y30 * ct * (5.0f * ct2 - 3.0f);
        float y31 = -C_Y31 * (5.0f * ct2 - 1.0f) * st * c1;
        float y32 =  C_Y32 * ct * st2 * c2;
        float y33 = -C_Y33 * st * st2 * c3;
        s3[lp * 7 + 0] = -y33;
        s3[lp * 7 + 1] =  y32;
        s3[lp * 7 + 2] = -y31;
        s3[lp * 7 + 3] =  y30;
        s3[lp * 7 + 4] =  y31;
        s3[lp * 7 + 5] =  y32;
        s3[lp * 7 + 6] =  y33;
    }
    __syncthreads();

    // ---- Phase 2: guard-free coalesced float4 streaming flush ----
    // l = 0: constant, 128 float4
    if (tid < PPB / 4) {
        float4 v = make_float4(C_Y00, C_Y00, C_Y00, C_Y00);
        __stcs((float4*)(out + base_pt) + tid, v);
    }

    // l = 1: 384 float4 (256 + 128)
    {
        float4* g = (float4*)(out + n + base_pt * 3);
        __stcs(g + tid, ((const float4*)s1buf)[tid]);
        if (tid < IN_F4 - THREADS)
            __stcs(g + tid + THREADS, ((const float4*)s1buf)[tid + THREADS]);
    }

    // l = 2: 640 float4 (256 + 256 + 128)
    {
        float4* g = (float4*)(out + 4 * n + base_pt * 5);
        __stcs(g + tid,           ((const float4*)s2)[tid]);
        __stcs(g + tid + THREADS, ((const float4*)s2)[tid + THREADS]);
        if (tid < (PPB * 5) / 4 - 2 * THREADS)
            __stcs(g + tid + 2 * THREADS, ((const float4*)s2)[tid + 2 * THREADS]);
    }

    // l = 3: 896 float4 (256*3 + 128)
    {
        float4* g = (float4*)(out + 9 * n + base_pt * 7);
        __stcs(g + tid,               ((const float4*)s3)[tid]);
        __stcs(g + tid + THREADS,     ((const float4*)s3)[tid + THREADS]);
        __stcs(g + tid + 2 * THREADS, ((const float4*)s3)[tid + 2 * THREADS]);
        if (tid < (PPB * 7) / 4 - 3 * THREADS)
            __stcs(g + tid + 3 * THREADS, ((const float4*)s3)[tid + 3 * THREADS]);
    }
}

// Scalar tail for points [start, n)
__global__ void sh_l3_tail_kernel(const float* __restrict__ dirs,
                                  float* __restrict__ out, int n, int start) {
    int i = start + blockIdx.x * blockDim.x + threadIdx.x;
    if (i >= n) return;
    float x = dirs[3 * i], y = dirs[3 * i + 1], z = dirs[3 * i + 2];
    float r = sqrtf(x * x + y * y + z * z);
    float ct = z / (r + 1e-8f), ct2 = ct * ct;
    float st = sqrtf(fmaxf(1.0f - ct2, 0.0f)), st2 = st * st;
    float rho2 = x * x + y * y, c1, c2, c3;
    if (rho2 > 0.0f) {
        float ir = rsqrtf(rho2);
        c1 = x * ir; c2 = 2.0f * c1 * c1 - 1.0f; c3 = c1 * (2.0f * c2 - 1.0f);
    } else { c1 = c2 = c3 = 1.0f; }
    out[i] = C_Y00;
    float y10 = C_Y10 * ct, y11 = -C_Y11 * st * c1;
    float* o1 = out + (size_t)n;
    o1[3 * i] = -y11; o1[3 * i + 1] = y10; o1[3 * i + 2] = y11;
    float y20 = C_Y20 * (3.0f * ct2 - 1.0f), y21 = -C_Y21 * ct * st * c1,
          y22 = C_Y22 * st2 * c2;
    float* o2 = out + (size_t)4 * n;
    o2[5 * i] = y22; o2[5 * i + 1] = -y21; o2[5 * i + 2] = y20;
    o2[5 * i + 3] = y21; o2[5 * i + 4] = y22;
    float y30 = C_Y30 * ct * (5.0f * ct2 - 3.0f),
          y31 = -C_Y31 * (5.0f * ct2 - 1.0f) * st * c1,
          y32 = C_Y32 * ct * st2 * c2, y33 = -C_Y33 * st * st2 * c3;
    float* o3 = out + (size_t)9 * n;
    o3[7 * i] = -y33; o3[7 * i + 1] = y32; o3[7 * i + 2] = -y31;
    o3[7 * i + 3] = y30; o3[7 * i + 4] = y31; o3[7 * i + 5] = y32;
    o3[7 * i + 6] = y33;
}

extern "C" void kernel_launch(void* const* d_in, const int* in_sizes, int n_in,
                              void* d_out, int out_size) {
    const float* dirs = (const float*)d_in[0];
    float* out = (float*)d_out;
    int n = in_sizes[0] / 3;

    int full = n / PPB;
    int start = full * PPB;

    if (full > 0)
        sh_l3_full_kernel<<<full, THREADS>>>(dirs, out, n);
    if (start < n) {
        int rem = n - start;
        sh_l3_tail_kernel<<<(rem + 255) / 256, 256>>>(dirs, out, n, start);
    }
}